// round 1
// baseline (speedup 1.0000x reference)
#include <cuda_runtime.h>
#include <math.h>
#include <stdint.h>
#include <stddef.h>

#define LQ   4096
#define NB   4
#define DIM  512
#define KDIM 128
#define NCH  32            // 4096 keys / 128-wide chunks
#define INV_TAU 30.0f

// ---------------- scratch (device globals; no allocation allowed) ----------------
__device__ float g_pq[(size_t)LQ * NB * KDIM];          // 8 MB  l2-normalized Wq
__device__ float g_pk[(size_t)LQ * NB * KDIM];          // 8 MB  l2-normalized Wk
__device__ float g_pv[(size_t)LQ * NB * DIM];           // 32 MB Wv
__device__ float g_sc[(size_t)NB * LQ * LQ];            // 256 MB exp(scores - m_chunk)
__device__ float g_corr[(size_t)NB * LQ * NCH];         // 2 MB  exp(m_chunk - m_fin)/S

// =================================================================================
// Projection GEMM: C[M,N] = A[M,512] @ W[N,512]^T + bias   (M = 16384)
// BM=BN=128, BK=32, 256 threads, 8x8 microtile (split 4+4), k-major smem tiles.
// =================================================================================
__global__ __launch_bounds__(256) void proj_gemm(const float* __restrict__ A,
                                                 const float* __restrict__ W,
                                                 const float* __restrict__ bias,
                                                 int dst, int N) {
    __shared__ float At[32 * 132];
    __shared__ float Wt[32 * 132];
    float* C = (dst == 0) ? g_pq : (dst == 1) ? g_pk : g_pv;

    const int tid = threadIdx.x;
    const int tx = tid & 15, ty = tid >> 4;
    const int bm = blockIdx.y * 128, bn = blockIdx.x * 128;

    float acc[8][8];
#pragma unroll
    for (int i = 0; i < 8; i++)
#pragma unroll
        for (int j = 0; j < 8; j++) acc[i][j] = 0.f;

    for (int k0 = 0; k0 < 512; k0 += 32) {
#pragma unroll
        for (int t = 0; t < 4; t++) {
            int u = tid + t * 256;        // float4 id, 1024 per tile
            int m = u >> 3;
            int kq = (u & 7) << 2;
            float4 va = *(const float4*)(A + (size_t)(bm + m) * 512 + k0 + kq);
            At[(kq + 0) * 132 + m] = va.x;
            At[(kq + 1) * 132 + m] = va.y;
            At[(kq + 2) * 132 + m] = va.z;
            At[(kq + 3) * 132 + m] = va.w;
            float4 vw = *(const float4*)(W + (size_t)(bn + m) * 512 + k0 + kq);
            Wt[(kq + 0) * 132 + m] = vw.x;
            Wt[(kq + 1) * 132 + m] = vw.y;
            Wt[(kq + 2) * 132 + m] = vw.z;
            Wt[(kq + 3) * 132 + m] = vw.w;
        }
        __syncthreads();
#pragma unroll 8
        for (int k = 0; k < 32; k++) {
            float a[8], bb[8];
            *(float4*)&a[0]  = *(const float4*)&At[k * 132 + ty * 4];
            *(float4*)&a[4]  = *(const float4*)&At[k * 132 + 64 + ty * 4];
            *(float4*)&bb[0] = *(const float4*)&Wt[k * 132 + tx * 4];
            *(float4*)&bb[4] = *(const float4*)&Wt[k * 132 + 64 + tx * 4];
#pragma unroll
            for (int i = 0; i < 8; i++)
#pragma unroll
                for (int j = 0; j < 8; j++) acc[i][j] = fmaf(a[i], bb[j], acc[i][j]);
        }
        __syncthreads();
    }

    float bv[8];
#pragma unroll
    for (int j = 0; j < 8; j++) {
        int col = bn + ((j < 4) ? tx * 4 + j : 64 + tx * 4 + (j - 4));
        bv[j] = bias[col];
    }
#pragma unroll
    for (int i = 0; i < 8; i++) {
        int row = bm + ((i < 4) ? ty * 4 + i : 64 + ty * 4 + (i - 4));
        float4 c0 = make_float4(acc[i][0] + bv[0], acc[i][1] + bv[1],
                                acc[i][2] + bv[2], acc[i][3] + bv[3]);
        float4 c1 = make_float4(acc[i][4] + bv[4], acc[i][5] + bv[5],
                                acc[i][6] + bv[6], acc[i][7] + bv[7]);
        *(float4*)(C + (size_t)row * N + bn + tx * 4) = c0;
        *(float4*)(C + (size_t)row * N + bn + 64 + tx * 4) = c1;
    }
}

// =================================================================================
// Row l2-normalize (KD = 128 cols), matches F.normalize eps semantics.
// =================================================================================
__global__ __launch_bounds__(128) void l2norm_kernel(int dst) {
    float* P = dst ? g_pk : g_pq;
    const int row = blockIdx.x;
    const int t = threadIdx.x;
    float v = P[(size_t)row * KDIM + t];
    float ss = v * v;
#pragma unroll
    for (int o = 16; o > 0; o >>= 1) ss += __shfl_xor_sync(0xffffffffu, ss, o);
    __shared__ float red[4];
    if ((t & 31) == 0) red[t >> 5] = ss;
    __syncthreads();
    float tot = red[0] + red[1] + red[2] + red[3];
    float sc = 1.0f / fmaxf(sqrtf(tot), 1e-12f);
    P[(size_t)row * KDIM + t] = v * sc;
}

// =================================================================================
// Scores + online softmax: per (batch, 128-query tile), sweep keys in 128-chunks.
// Writes exp(30*dot - m_chunk) to g_sc, and per-(row,chunk) correction to g_corr.
// 256 threads, 8x8 microtile of the 128x128 score tile; rows of a query live in
// a fixed 16-lane tx-group -> shuffle reductions for max / sum.
// =================================================================================
__global__ __launch_bounds__(256) void scores_kernel() {
    extern __shared__ float sm[];
    float* sqt  = sm;                    // [k=128][q=128+pad]
    float* skt  = sqt + 128 * 132;       // [k=128][s=128+pad]
    float* mch  = skt + 128 * 132;       // [128][NCH]
    float* mfin = mch + 128 * NCH;       // [128]
    float* rsf  = mfin + 128;            // [128]

    const int b = blockIdx.y;
    const int q0 = blockIdx.x * 128;
    const int tid = threadIdx.x;
    const int tx = tid & 15, ty = tid >> 4;

    // Load Q tile transposed (k-major)
#pragma unroll 4
    for (int t = 0; t < 16; t++) {
        int u = tid + t * 256;
        int row = u >> 5;
        int kq = (u & 31) << 2;
        float4 v = *(const float4*)(g_pq + ((size_t)(q0 + row) * NB + b) * KDIM + kq);
        sqt[(kq + 0) * 132 + row] = v.x;
        sqt[(kq + 1) * 132 + row] = v.y;
        sqt[(kq + 2) * 132 + row] = v.z;
        sqt[(kq + 3) * 132 + row] = v.w;
    }

    float m_run[8], s_run[8];
    int rowi[8];
#pragma unroll
    for (int i = 0; i < 8; i++) {
        m_run[i] = -INFINITY;
        s_run[i] = 0.f;
        rowi[i] = (i < 4) ? ty * 4 + i : 64 + ty * 4 + (i - 4);
    }

    for (int kc = 0; kc < NCH; kc++) {
        const int s0 = kc * 128;
#pragma unroll 4
        for (int t = 0; t < 16; t++) {
            int u = tid + t * 256;
            int row = u >> 5;
            int kq = (u & 31) << 2;
            float4 v = *(const float4*)(g_pk + ((size_t)(s0 + row) * NB + b) * KDIM + kq);
            skt[(kq + 0) * 132 + row] = v.x;
            skt[(kq + 1) * 132 + row] = v.y;
            skt[(kq + 2) * 132 + row] = v.z;
            skt[(kq + 3) * 132 + row] = v.w;
        }
        __syncthreads();

        float acc[8][8];
#pragma unroll
        for (int i = 0; i < 8; i++)
#pragma unroll
            for (int j = 0; j < 8; j++) acc[i][j] = 0.f;

#pragma unroll 8
        for (int k = 0; k < 128; k++) {
            float a[8], bb[8];
            *(float4*)&a[0]  = *(const float4*)&sqt[k * 132 + ty * 4];
            *(float4*)&a[4]  = *(const float4*)&sqt[k * 132 + 64 + ty * 4];
            *(float4*)&bb[0] = *(const float4*)&skt[k * 132 + tx * 4];
            *(float4*)&bb[4] = *(const float4*)&skt[k * 132 + 64 + tx * 4];
#pragma unroll
            for (int i = 0; i < 8; i++)
#pragma unroll
                for (int j = 0; j < 8; j++) acc[i][j] = fmaf(a[i], bb[j], acc[i][j]);
        }
        __syncthreads();   // done reading skt; next chunk's loads may begin after

        // online softmax update (per row across the 16-lane tx group)
#pragma unroll
        for (int i = 0; i < 8; i++) {
            float rm = -INFINITY;
#pragma unroll
            for (int j = 0; j < 8; j++) {
                acc[i][j] *= INV_TAU;
                rm = fmaxf(rm, acc[i][j]);
            }
#pragma unroll
            for (int o = 1; o < 16; o <<= 1)
                rm = fmaxf(rm, __shfl_xor_sync(0xffffffffu, rm, o));
            float m_new = fmaxf(m_run[i], rm);
            float rs = 0.f;
#pragma unroll
            for (int j = 0; j < 8; j++) {
                acc[i][j] = __expf(acc[i][j] - m_new);
                rs += acc[i][j];
            }
#pragma unroll
            for (int o = 1; o < 16; o <<= 1)
                rs += __shfl_xor_sync(0xffffffffu, rs, o);
            s_run[i] = s_run[i] * __expf(m_run[i] - m_new) + rs;
            m_run[i] = m_new;
            if (tx == 0) mch[rowi[i] * NCH + kc] = m_new;

            size_t base = ((size_t)b * LQ + q0 + rowi[i]) * LQ + s0;
            *(float4*)(g_sc + base + tx * 4) =
                make_float4(acc[i][0], acc[i][1], acc[i][2], acc[i][3]);
            *(float4*)(g_sc + base + 64 + tx * 4) =
                make_float4(acc[i][4], acc[i][5], acc[i][6], acc[i][7]);
        }
    }

    if (tx == 0) {
#pragma unroll
        for (int i = 0; i < 8; i++) {
            mfin[rowi[i]] = m_run[i];
            rsf[rowi[i]] = 1.0f / s_run[i];
        }
    }
    __syncthreads();
    for (int idx = tid; idx < 128 * NCH; idx += 256) {
        int row = idx >> 5;          // NCH == 32
        int kc = idx & 31;
        g_corr[((size_t)b * LQ + q0 + row) * NCH + kc] =
            __expf(mch[row * NCH + kc] - mfin[row]) * rsf[row];
    }
}

// =================================================================================
// out[q,b,d] = sum_s affinity * V ; affinity rebuilt as stored_e * corr (no exp).
// BM=128 (q), BN=128 (d), BK=32 (s), 256 threads, 8x8 microtile.
// =================================================================================
__global__ __launch_bounds__(256) void out_gemm(float* __restrict__ out) {
    __shared__ float At[32 * 132];   // [s][q] (transposed on load)
    __shared__ float Vs[32 * 132];   // [s][d] (natural)
    const int b = blockIdx.z;
    const int q0 = blockIdx.y * 128;
    const int d0 = blockIdx.x * 128;
    const int tid = threadIdx.x;
    const int tx = tid & 15, ty = tid >> 4;

    float acc[8][8];
#pragma unroll
    for (int i = 0; i < 8; i++)
#pragma unroll
        for (int j = 0; j < 8; j++) acc[i][j] = 0.f;

    for (int ch = 0; ch < NCH; ch++) {
        float fr[4];
#pragma unroll
        for (int t = 0; t < 4; t++) {
            int q = (tid + t * 256) >> 3;
            fr[t] = g_corr[((size_t)b * LQ + q0 + q) * NCH + ch];
        }
        for (int s1 = 0; s1 < 4; s1++) {
            const int s0 = ch * 128 + s1 * 32;
            __syncthreads();
#pragma unroll
            for (int t = 0; t < 4; t++) {
                int u = tid + t * 256;
                int q = u >> 3;
                int sq = (u & 7) << 2;
                float4 v = *(const float4*)(g_sc + ((size_t)b * LQ + q0 + q) * LQ + s0 + sq);
                float f = fr[t];
                At[(sq + 0) * 132 + q] = v.x * f;
                At[(sq + 1) * 132 + q] = v.y * f;
                At[(sq + 2) * 132 + q] = v.z * f;
                At[(sq + 3) * 132 + q] = v.w * f;
            }
#pragma unroll
            for (int t = 0; t < 4; t++) {
                int u = tid + t * 256;
                int kk = u >> 5;
                int dq = (u & 31) << 2;
                *(float4*)&Vs[kk * 132 + dq] =
                    *(const float4*)(g_pv + ((size_t)(s0 + kk) * NB + b) * DIM + d0 + dq);
            }
            __syncthreads();
#pragma unroll 8
            for (int k = 0; k < 32; k++) {
                float a[8], vv[8];
                *(float4*)&a[0]  = *(const float4*)&At[k * 132 + ty * 4];
                *(float4*)&a[4]  = *(const float4*)&At[k * 132 + 64 + ty * 4];
                *(float4*)&vv[0] = *(const float4*)&Vs[k * 132 + tx * 4];
                *(float4*)&vv[4] = *(const float4*)&Vs[k * 132 + 64 + tx * 4];
#pragma unroll
                for (int i = 0; i < 8; i++)
#pragma unroll
                    for (int j = 0; j < 8; j++) acc[i][j] = fmaf(a[i], vv[j], acc[i][j]);
            }
        }
    }

#pragma unroll
    for (int i = 0; i < 8; i++) {
        int row = q0 + ((i < 4) ? ty * 4 + i : 64 + ty * 4 + (i - 4));
        size_t ob = ((size_t)row * NB + b) * DIM + d0;
        *(float4*)(out + ob + tx * 4) =
            make_float4(acc[i][0], acc[i][1], acc[i][2], acc[i][3]);
        *(float4*)(out + ob + 64 + tx * 4) =
            make_float4(acc[i][4], acc[i][5], acc[i][6], acc[i][7]);
    }
}

// =================================================================================
extern "C" void kernel_launch(void* const* d_in, const int* in_sizes, int n_in,
                              void* d_out, int out_size) {
    (void)in_sizes; (void)n_in; (void)out_size;
    const float* query = (const float*)d_in[0];
    const float* key   = (const float*)d_in[1];
    const float* value = (const float*)d_in[2];
    const float* WKw   = (const float*)d_in[3];
    const float* WKb   = (const float*)d_in[4];
    const float* WVw   = (const float*)d_in[5];
    const float* WVb   = (const float*)d_in[6];
    float* out = (float*)d_out;

    const size_t sc_smem =
        (size_t)(2 * 128 * 132 + 128 * NCH + 256) * sizeof(float);  // 152,576 B
    cudaFuncSetAttribute(scores_kernel,
                         cudaFuncAttributeMaxDynamicSharedMemorySize, (int)sc_smem);

    proj_gemm<<<dim3(1, 128), 256>>>(query, WKw, WKb, 0, KDIM);
    proj_gemm<<<dim3(1, 128), 256>>>(key,   WKw, WKb, 1, KDIM);
    proj_gemm<<<dim3(4, 128), 256>>>(value, WVw, WVb, 2, DIM);
    l2norm_kernel<<<LQ * NB, 128>>>(0);
    l2norm_kernel<<<LQ * NB, 128>>>(1);
    scores_kernel<<<dim3(LQ / 128, NB), 256, sc_smem>>>();
    out_gemm<<<dim3(DIM / 128, LQ / 128, NB), 256>>>(out);
}

// round 2
// speedup vs baseline: 1.2609x; 1.2609x over previous
#include <cuda_runtime.h>
#include <math.h>
#include <stdint.h>
#include <stddef.h>

#define LQ   4096
#define NB   4
#define DIM  512
#define KDIM 128
#define NCH  32
#define MTOT (LQ * NB)

// ---------------- scratch ----------------
__device__ float g_pq[(size_t)MTOT * KDIM];
__device__ float g_pk[(size_t)MTOT * KDIM];
__device__ float g_pv[(size_t)MTOT * DIM];
__device__ float g_sc[(size_t)NB * LQ * LQ];
__device__ float g_corr[(size_t)NB * LQ * NCH];

// ---------------- tf32 helpers ----------------
__device__ __forceinline__ uint32_t f2tf(float x) {
    uint32_t u;
    asm("cvt.rna.tf32.f32 %0, %1;" : "=r"(u) : "f"(x));
    return u;
}
__device__ __forceinline__ void split_tf(float x, uint32_t& h, uint32_t& l) {
    h = f2tf(x);
    l = f2tf(x - __uint_as_float(h));
}
__device__ __forceinline__ void mma8(float c[4], uint32_t a0, uint32_t a1,
                                     uint32_t a2, uint32_t a3,
                                     uint32_t b0, uint32_t b1) {
    asm volatile(
        "mma.sync.aligned.m16n8k8.row.col.f32.tf32.tf32.f32 "
        "{%0,%1,%2,%3},{%4,%5,%6,%7},{%8,%9},{%0,%1,%2,%3};"
        : "+f"(c[0]), "+f"(c[1]), "+f"(c[2]), "+f"(c[3])
        : "r"(a0), "r"(a1), "r"(a2), "r"(a3), "r"(b0), "r"(b1));
}

// =================================================================================
// Projection: C[M,N] = A[M,512] @ W[N,512]^T + bias  (tf32x3), optional fused l2norm.
// Block 128x128, 8 warps as 4(m)x2(n), warp tile 32x64.
// =================================================================================
template <bool NORM>
__global__ __launch_bounds__(256) void proj_kernel(const float* __restrict__ A,
                                                   const float* __restrict__ W,
                                                   const float* __restrict__ bias,
                                                   int dst, int N) {
    extern __shared__ __align__(16) uint32_t sm[];
    uint32_t* Ah = sm;                    // [128][36]
    uint32_t* Al = Ah + 128 * 36;
    uint32_t* Wh = Al + 128 * 36;
    uint32_t* Wl = Wh + 128 * 36;
    float* pnorm = (float*)(Wl + 128 * 36);  // [2][128]

    float* C = (dst == 0) ? g_pq : (dst == 1) ? g_pk : g_pv;

    const int tid = threadIdx.x;
    const int lane = tid & 31, w = tid >> 5;
    const int g = lane >> 2, tig = lane & 3;
    const int wq = w >> 1, ws = w & 1;
    const int bm = blockIdx.y * 128, bn = blockIdx.x * 128;

    float c[2][8][4];
#pragma unroll
    for (int mt = 0; mt < 2; mt++)
#pragma unroll
        for (int j = 0; j < 8; j++)
#pragma unroll
            for (int v = 0; v < 4; v++) c[mt][j][v] = 0.f;

    for (int k0 = 0; k0 < DIM; k0 += 32) {
        __syncthreads();
#pragma unroll
        for (int t = 0; t < 4; t++) {
            int u = tid + t * 256;
            int m = u >> 3, kq = (u & 7) << 2;
            float4 va = *(const float4*)(A + (size_t)(bm + m) * DIM + k0 + kq);
            split_tf(va.x, Ah[m * 36 + kq + 0], Al[m * 36 + kq + 0]);
            split_tf(va.y, Ah[m * 36 + kq + 1], Al[m * 36 + kq + 1]);
            split_tf(va.z, Ah[m * 36 + kq + 2], Al[m * 36 + kq + 2]);
            split_tf(va.w, Ah[m * 36 + kq + 3], Al[m * 36 + kq + 3]);
            float4 vw = *(const float4*)(W + (size_t)(bn + m) * DIM + k0 + kq);
            split_tf(vw.x, Wh[m * 36 + kq + 0], Wl[m * 36 + kq + 0]);
            split_tf(vw.y, Wh[m * 36 + kq + 1], Wl[m * 36 + kq + 1]);
            split_tf(vw.z, Wh[m * 36 + kq + 2], Wl[m * 36 + kq + 2]);
            split_tf(vw.w, Wh[m * 36 + kq + 3], Wl[m * 36 + kq + 3]);
        }
        __syncthreads();
#pragma unroll
        for (int kk = 0; kk < 4; kk++) {
            const int kc = kk * 8 + tig;
            uint32_t ah[2][4], al[2][4];
#pragma unroll
            for (int mt = 0; mt < 2; mt++) {
                int r = wq * 32 + mt * 16 + g;
                ah[mt][0] = Ah[r * 36 + kc];
                ah[mt][1] = Ah[(r + 8) * 36 + kc];
                ah[mt][2] = Ah[r * 36 + kc + 4];
                ah[mt][3] = Ah[(r + 8) * 36 + kc + 4];
                al[mt][0] = Al[r * 36 + kc];
                al[mt][1] = Al[(r + 8) * 36 + kc];
                al[mt][2] = Al[r * 36 + kc + 4];
                al[mt][3] = Al[(r + 8) * 36 + kc + 4];
            }
#pragma unroll
            for (int j = 0; j < 8; j++) {
                int n = ws * 64 + j * 8 + g;
                uint32_t bh0 = Wh[n * 36 + kc], bh1 = Wh[n * 36 + kc + 4];
                uint32_t bl0 = Wl[n * 36 + kc], bl1 = Wl[n * 36 + kc + 4];
#pragma unroll
                for (int mt = 0; mt < 2; mt++) {
                    mma8(c[mt][j], ah[mt][0], ah[mt][1], ah[mt][2], ah[mt][3], bl0, bl1);
                    mma8(c[mt][j], al[mt][0], al[mt][1], al[mt][2], al[mt][3], bh0, bh1);
                    mma8(c[mt][j], ah[mt][0], ah[mt][1], ah[mt][2], ah[mt][3], bh0, bh1);
                }
            }
        }
    }

    // bias
#pragma unroll
    for (int j = 0; j < 8; j++) {
        int col = bn + ws * 64 + j * 8 + 2 * tig;
        float b0 = bias[col], b1 = bias[col + 1];
#pragma unroll
        for (int mt = 0; mt < 2; mt++) {
            c[mt][j][0] += b0; c[mt][j][1] += b1;
            c[mt][j][2] += b0; c[mt][j][3] += b1;
        }
    }

    if (NORM) {
        float ss[2][2];
#pragma unroll
        for (int mt = 0; mt < 2; mt++) { ss[mt][0] = 0.f; ss[mt][1] = 0.f; }
#pragma unroll
        for (int mt = 0; mt < 2; mt++)
#pragma unroll
            for (int j = 0; j < 8; j++) {
                ss[mt][0] += c[mt][j][0] * c[mt][j][0] + c[mt][j][1] * c[mt][j][1];
                ss[mt][1] += c[mt][j][2] * c[mt][j][2] + c[mt][j][3] * c[mt][j][3];
            }
#pragma unroll
        for (int mt = 0; mt < 2; mt++)
#pragma unroll
            for (int h = 0; h < 2; h++) {
                ss[mt][h] += __shfl_xor_sync(0xffffffffu, ss[mt][h], 1);
                ss[mt][h] += __shfl_xor_sync(0xffffffffu, ss[mt][h], 2);
            }
        if (tig == 0) {
#pragma unroll
            for (int mt = 0; mt < 2; mt++)
#pragma unroll
                for (int h = 0; h < 2; h++)
                    pnorm[ws * 128 + wq * 32 + mt * 16 + g + 8 * h] = ss[mt][h];
        }
        __syncthreads();
    }

#pragma unroll
    for (int mt = 0; mt < 2; mt++)
#pragma unroll
        for (int h = 0; h < 2; h++) {
            int row = wq * 32 + mt * 16 + g + 8 * h;
            float scale = 1.f;
            if (NORM) {
                float n2 = pnorm[row] + pnorm[128 + row];
                scale = 1.f / fmaxf(sqrtf(n2), 1e-12f);
            }
            size_t base = (size_t)(bm + row) * N + bn + ws * 64;
#pragma unroll
            for (int j = 0; j < 8; j++) {
                float2 v = make_float2(c[mt][j][2 * h] * scale,
                                       c[mt][j][2 * h + 1] * scale);
                *(float2*)(C + base + j * 8 + 2 * tig) = v;
            }
        }
}

// =================================================================================
// Scores + online softmax (tf32x3). Block = 128q x (all keys, 128-chunks), b fixed.
// Q (128x128) resident hi/lo; K chunk loaded in two 64-wide k halves.
// =================================================================================
__global__ __launch_bounds__(256) void scores_kernel() {
    extern __shared__ __align__(16) uint32_t sm[];
    uint32_t* Qh = sm;                    // [128][132]
    uint32_t* Ql = Qh + 128 * 132;
    uint32_t* Kh = Ql + 128 * 132;        // [128][68]
    uint32_t* Kl = Kh + 128 * 68;
    float* fb    = (float*)(Kl + 128 * 68);
    float* m_run = fb;            // [128]
    float* s_run = fb + 128;      // [128]
    float* mnew  = fb + 256;      // [128]
    float* pmax  = fb + 384;      // [2][128]
    float* psum  = fb + 640;      // [2][128]
    float* mch   = fb + 896;      // [128][33] padded

    const int tid = threadIdx.x;
    const int lane = tid & 31, w = tid >> 5;
    const int g = lane >> 2, tig = lane & 3;
    const int wq = w >> 1, ws = w & 1;
    const int b = blockIdx.y;
    const int q0 = blockIdx.x * 128;

    if (tid < 128) { m_run[tid] = -INFINITY; s_run[tid] = 0.f; }

    // Q resident, split hi/lo
#pragma unroll
    for (int t = 0; t < 16; t++) {
        int u = tid + t * 256;
        int q = u >> 5, c4 = (u & 31) << 2;
        float4 v = *(const float4*)(g_pq + (size_t)((q0 + q) * NB + b) * KDIM + c4);
        split_tf(v.x, Qh[q * 132 + c4 + 0], Ql[q * 132 + c4 + 0]);
        split_tf(v.y, Qh[q * 132 + c4 + 1], Ql[q * 132 + c4 + 1]);
        split_tf(v.z, Qh[q * 132 + c4 + 2], Ql[q * 132 + c4 + 2]);
        split_tf(v.w, Qh[q * 132 + c4 + 3], Ql[q * 132 + c4 + 3]);
    }

    for (int ch = 0; ch < NCH; ch++) {
        const int s0 = ch * 128;
        float c[2][8][4];
#pragma unroll
        for (int mt = 0; mt < 2; mt++)
#pragma unroll
            for (int j = 0; j < 8; j++)
#pragma unroll
                for (int v = 0; v < 4; v++) c[mt][j][v] = 0.f;

        for (int kh = 0; kh < 2; kh++) {
            __syncthreads();
#pragma unroll
            for (int t = 0; t < 8; t++) {
                int u = tid + t * 256;
                int s = u >> 4, c4 = (u & 15) << 2;
                float4 v = *(const float4*)(g_pk +
                        (size_t)((s0 + s) * NB + b) * KDIM + kh * 64 + c4);
                split_tf(v.x, Kh[s * 68 + c4 + 0], Kl[s * 68 + c4 + 0]);
                split_tf(v.y, Kh[s * 68 + c4 + 1], Kl[s * 68 + c4 + 1]);
                split_tf(v.z, Kh[s * 68 + c4 + 2], Kl[s * 68 + c4 + 2]);
                split_tf(v.w, Kh[s * 68 + c4 + 3], Kl[s * 68 + c4 + 3]);
            }
            __syncthreads();
#pragma unroll
            for (int kk = 0; kk < 8; kk++) {
                const int kcQ = kh * 64 + kk * 8 + tig;
                const int kcK = kk * 8 + tig;
                uint32_t ah[2][4], al[2][4];
#pragma unroll
                for (int mt = 0; mt < 2; mt++) {
                    int r = wq * 32 + mt * 16 + g;
                    ah[mt][0] = Qh[r * 132 + kcQ];
                    ah[mt][1] = Qh[(r + 8) * 132 + kcQ];
                    ah[mt][2] = Qh[r * 132 + kcQ + 4];
                    ah[mt][3] = Qh[(r + 8) * 132 + kcQ + 4];
                    al[mt][0] = Ql[r * 132 + kcQ];
                    al[mt][1] = Ql[(r + 8) * 132 + kcQ];
                    al[mt][2] = Ql[r * 132 + kcQ + 4];
                    al[mt][3] = Ql[(r + 8) * 132 + kcQ + 4];
                }
#pragma unroll
                for (int j = 0; j < 8; j++) {
                    int n = ws * 64 + j * 8 + g;
                    uint32_t bh0 = Kh[n * 68 + kcK], bh1 = Kh[n * 68 + kcK + 4];
                    uint32_t bl0 = Kl[n * 68 + kcK], bl1 = Kl[n * 68 + kcK + 4];
#pragma unroll
                    for (int mt = 0; mt < 2; mt++) {
                        mma8(c[mt][j], ah[mt][0], ah[mt][1], ah[mt][2], ah[mt][3], bl0, bl1);
                        mma8(c[mt][j], al[mt][0], al[mt][1], al[mt][2], al[mt][3], bh0, bh1);
                        mma8(c[mt][j], ah[mt][0], ah[mt][1], ah[mt][2], ah[mt][3], bh0, bh1);
                    }
                }
            }
        }

        // ---- softmax over this 128-key chunk ----
        float rmax[2][2];
#pragma unroll
        for (int mt = 0; mt < 2; mt++)
#pragma unroll
            for (int h = 0; h < 2; h++) {
                float m = -INFINITY;
#pragma unroll
                for (int j = 0; j < 8; j++)
                    m = fmaxf(m, fmaxf(c[mt][j][2 * h], c[mt][j][2 * h + 1]));
                m = fmaxf(m, __shfl_xor_sync(0xffffffffu, m, 1));
                m = fmaxf(m, __shfl_xor_sync(0xffffffffu, m, 2));
                rmax[mt][h] = m;
            }
        if (tig == 0) {
#pragma unroll
            for (int mt = 0; mt < 2; mt++)
#pragma unroll
                for (int h = 0; h < 2; h++)
                    pmax[ws * 128 + wq * 32 + mt * 16 + g + 8 * h] = rmax[mt][h];
        }
        __syncthreads();
        if (tid < 128) {
            float mo = m_run[tid];
            float mn = fmaxf(mo, 30.f * fmaxf(pmax[tid], pmax[128 + tid]));
            mnew[tid] = mn;
            m_run[tid] = mn;
            s_run[tid] *= __expf(mo - mn);
            mch[tid * 33 + ch] = mn;
        }
        __syncthreads();
#pragma unroll
        for (int mt = 0; mt < 2; mt++)
#pragma unroll
            for (int h = 0; h < 2; h++) {
                int row = wq * 32 + mt * 16 + g + 8 * h;
                float mr = mnew[row];
                size_t base = ((size_t)b * LQ + q0 + row) * LQ + s0 + ws * 64;
                float rs = 0.f;
#pragma unroll
                for (int j = 0; j < 8; j++) {
                    float e0 = __expf(fmaf(30.f, c[mt][j][2 * h], -mr));
                    float e1 = __expf(fmaf(30.f, c[mt][j][2 * h + 1], -mr));
                    rs += e0 + e1;
                    *(float2*)(g_sc + base + j * 8 + 2 * tig) = make_float2(e0, e1);
                }
                rs += __shfl_xor_sync(0xffffffffu, rs, 1);
                rs += __shfl_xor_sync(0xffffffffu, rs, 2);
                if (tig == 0) psum[ws * 128 + row] = rs;
            }
        __syncthreads();
        if (tid < 128) s_run[tid] += psum[tid] + psum[128 + tid];
        // next iteration's leading __syncthreads orders this vs. K reload
    }

    __syncthreads();
    if (tid < 128) s_run[tid] = 1.f / s_run[tid];
    __syncthreads();
#pragma unroll
    for (int t = 0; t < 16; t++) {
        int u = tid + t * 256;
        int q = u >> 5, ch = u & 31;
        g_corr[((size_t)b * LQ + q0 + q) * NCH + ch] =
            __expf(mch[q * 33 + ch] - m_run[q]) * s_run[q];
    }
}

// =================================================================================
// out = P @ V (tf32x3). P rebuilt as g_sc * corr at smem-load time (no exp).
// Block 128q x 128d, k-chunks of 32 keys.
// =================================================================================
__global__ __launch_bounds__(256) void out_kernel(float* __restrict__ out) {
    extern __shared__ __align__(16) uint32_t sm[];
    uint32_t* Ph = sm;              // [128][36]
    uint32_t* Pl = Ph + 128 * 36;
    uint32_t* Vh = Pl + 128 * 36;   // [32][136]
    uint32_t* Vl = Vh + 32 * 136;
    float* csm = (float*)(Vl + 32 * 136);  // [128]

    const int tid = threadIdx.x;
    const int lane = tid & 31, w = tid >> 5;
    const int g = lane >> 2, tig = lane & 3;
    const int wq = w >> 1, ws = w & 1;
    const int b = blockIdx.z;
    const int q0 = blockIdx.y * 128;
    const int d0 = blockIdx.x * 128;

    float c[2][8][4];
#pragma unroll
    for (int mt = 0; mt < 2; mt++)
#pragma unroll
        for (int j = 0; j < 8; j++)
#pragma unroll
            for (int v = 0; v < 4; v++) c[mt][j][v] = 0.f;

    for (int ch = 0; ch < NCH; ch++) {
        __syncthreads();
        if (tid < 128)
            csm[tid] = g_corr[((size_t)b * LQ + q0 + tid) * NCH + ch];
        for (int s1 = 0; s1 < 4; s1++) {
            const int s0 = ch * 128 + s1 * 32;
            __syncthreads();
#pragma unroll
            for (int t = 0; t < 4; t++) {
                int u = tid + t * 256;
                int q = u >> 3, s4 = (u & 7) << 2;
                float4 v = *(const float4*)(g_sc +
                        ((size_t)b * LQ + q0 + q) * LQ + s0 + s4);
                float f = csm[q];
                split_tf(v.x * f, Ph[q * 36 + s4 + 0], Pl[q * 36 + s4 + 0]);
                split_tf(v.y * f, Ph[q * 36 + s4 + 1], Pl[q * 36 + s4 + 1]);
                split_tf(v.z * f, Ph[q * 36 + s4 + 2], Pl[q * 36 + s4 + 2]);
                split_tf(v.w * f, Ph[q * 36 + s4 + 3], Pl[q * 36 + s4 + 3]);
            }
#pragma unroll
            for (int t = 0; t < 4; t++) {
                int u = tid + t * 256;
                int s = u >> 5, d4 = (u & 31) << 2;
                float4 v = *(const float4*)(g_pv +
                        (size_t)((s0 + s) * NB + b) * DIM + d0 + d4);
                split_tf(v.x, Vh[s * 136 + d4 + 0], Vl[s * 136 + d4 + 0]);
                split_tf(v.y, Vh[s * 136 + d4 + 1], Vl[s * 136 + d4 + 1]);
                split_tf(v.z, Vh[s * 136 + d4 + 2], Vl[s * 136 + d4 + 2]);
                split_tf(v.w, Vh[s * 136 + d4 + 3], Vl[s * 136 + d4 + 3]);
            }
            __syncthreads();
#pragma unroll
            for (int kk = 0; kk < 4; kk++) {
                const int kc = kk * 8 + tig;
                uint32_t ah[2][4], al[2][4];
#pragma unroll
                for (int mt = 0; mt < 2; mt++) {
                    int r = wq * 32 + mt * 16 + g;
                    ah[mt][0] = Ph[r * 36 + kc];
                    ah[mt][1] = Ph[(r + 8) * 36 + kc];
                    ah[mt][2] = Ph[r * 36 + kc + 4];
                    ah[mt][3] = Ph[(r + 8) * 36 + kc + 4];
                    al[mt][0] = Pl[r * 36 + kc];
                    al[mt][1] = Pl[(r + 8) * 36 + kc];
                    al[mt][2] = Pl[r * 36 + kc + 4];
                    al[mt][3] = Pl[(r + 8) * 36 + kc + 4];
                }
#pragma unroll
                for (int j = 0; j < 8; j++) {
                    int n = ws * 64 + j * 8 + g;
                    uint32_t bh0 = Vh[kc * 136 + n], bh1 = Vh[(kc + 4) * 136 + n];
                    uint32_t bl0 = Vl[kc * 136 + n], bl1 = Vl[(kc + 4) * 136 + n];
#pragma unroll
                    for (int mt = 0; mt < 2; mt++) {
                        mma8(c[mt][j], ah[mt][0], ah[mt][1], ah[mt][2], ah[mt][3], bl0, bl1);
                        mma8(c[mt][j], al[mt][0], al[mt][1], al[mt][2], al[mt][3], bh0, bh1);
                        mma8(c[mt][j], ah[mt][0], ah[mt][1], ah[mt][2], ah[mt][3], bh0, bh1);
                    }
                }
            }
        }
    }

#pragma unroll
    for (int mt = 0; mt < 2; mt++)
#pragma unroll
        for (int h = 0; h < 2; h++) {
            int row = wq * 32 + mt * 16 + g + 8 * h;
            size_t base = ((size_t)(q0 + row) * NB + b) * DIM + d0 + ws * 64;
#pragma unroll
            for (int j = 0; j < 8; j++)
                *(float2*)(out + base + j * 8 + 2 * tig) =
                    make_float2(c[mt][j][2 * h], c[mt][j][2 * h + 1]);
        }
}

// =================================================================================
extern "C" void kernel_launch(void* const* d_in, const int* in_sizes, int n_in,
                              void* d_out, int out_size) {
    (void)in_sizes; (void)n_in; (void)out_size;
    const float* query = (const float*)d_in[0];
    const float* key   = (const float*)d_in[1];
    const float* value = (const float*)d_in[2];
    const float* WKw   = (const float*)d_in[3];
    const float* WKb   = (const float*)d_in[4];
    const float* WVw   = (const float*)d_in[5];
    const float* WVb   = (const float*)d_in[6];
    float* out = (float*)d_out;

    const size_t SMP = (size_t)(4 * 128 * 36 + 256) * 4;                  //  74,752
    const size_t SMS = (size_t)(2 * 128 * 132 + 2 * 128 * 68 + 5120) * 4; // 225,280
    const size_t SMO = (size_t)(2 * 128 * 36 + 2 * 32 * 136 + 128) * 4;   //  72,192

    cudaFuncSetAttribute(proj_kernel<true>,
                         cudaFuncAttributeMaxDynamicSharedMemorySize, (int)SMP);
    cudaFuncSetAttribute(proj_kernel<false>,
                         cudaFuncAttributeMaxDynamicSharedMemorySize, (int)SMP);
    cudaFuncSetAttribute(scores_kernel,
                         cudaFuncAttributeMaxDynamicSharedMemorySize, (int)SMS);
    cudaFuncSetAttribute(out_kernel,
                         cudaFuncAttributeMaxDynamicSharedMemorySize, (int)SMO);

    proj_kernel<true><<<dim3(1, 128), 256, SMP>>>(query, WKw, WKb, 0, KDIM);
    proj_kernel<true><<<dim3(1, 128), 256, SMP>>>(key,   WKw, WKb, 1, KDIM);
    proj_kernel<false><<<dim3(4, 128), 256, SMP>>>(value, WVw, WVb, 2, DIM);
    scores_kernel<<<dim3(LQ / 128, NB), 256, SMS>>>();
    out_kernel<<<dim3(DIM / 128, LQ / 128, NB), 256, SMO>>>(out);
}

// round 4
// speedup vs baseline: 2.3210x; 1.8408x over previous
#include <cuda_runtime.h>
#include <cuda_bf16.h>
#include <math.h>
#include <stdint.h>
#include <stddef.h>

#define LQ   4096
#define NB   4
#define DIM  512
#define KDIM 128
#define NCH  32
#define MTOT (LQ * NB)

// ---------------- scratch ----------------
__device__ float g_pq[(size_t)MTOT * KDIM];
__device__ float g_pk[(size_t)MTOT * KDIM];
__device__ float g_pvT[(size_t)NB * DIM * LQ];    // [b][d][l]
__device__ float g_sc[(size_t)NB * LQ * LQ];
__device__ float g_corr[(size_t)NB * LQ * NCH];

// ---------------- tf32 helpers (projections only) ----------------
__device__ __forceinline__ uint32_t f2tf(float x) {
    uint32_t u;
    asm("cvt.rna.tf32.f32 %0, %1;" : "=r"(u) : "f"(x));
    return u;
}
__device__ __forceinline__ void split_tf(float x, uint32_t& h, uint32_t& l) {
    h = f2tf(x);
    l = f2tf(x - __uint_as_float(h));
}
__device__ __forceinline__ void mma8(float c[4], uint32_t a0, uint32_t a1,
                                     uint32_t a2, uint32_t a3,
                                     uint32_t b0, uint32_t b1) {
    asm volatile(
        "mma.sync.aligned.m16n8k8.row.col.f32.tf32.tf32.f32 "
        "{%0,%1,%2,%3},{%4,%5,%6,%7},{%8,%9},{%0,%1,%2,%3};"
        : "+f"(c[0]), "+f"(c[1]), "+f"(c[2]), "+f"(c[3])
        : "r"(a0), "r"(a1), "r"(a2), "r"(a3), "r"(b0), "r"(b1));
}

// ---------------- bf16 helpers ----------------
__device__ __forceinline__ void split_pack(float x, float y,
                                           uint32_t& h, uint32_t& l) {
    __nv_bfloat16 bx = __float2bfloat16_rn(x);
    __nv_bfloat16 by = __float2bfloat16_rn(y);
    float rx = x - __bfloat162float(bx);
    float ry = y - __bfloat162float(by);
    __nv_bfloat16 cx = __float2bfloat16_rn(rx);
    __nv_bfloat16 cy = __float2bfloat16_rn(ry);
    h = ((uint32_t)__bfloat16_as_ushort(by) << 16) | __bfloat16_as_ushort(bx);
    l = ((uint32_t)__bfloat16_as_ushort(cy) << 16) | __bfloat16_as_ushort(cx);
}
__device__ __forceinline__ void mma16(float c[4], uint32_t a0, uint32_t a1,
                                      uint32_t a2, uint32_t a3,
                                      uint32_t b0, uint32_t b1) {
    asm volatile(
        "mma.sync.aligned.m16n8k16.row.col.f32.bf16.bf16.f32 "
        "{%0,%1,%2,%3},{%4,%5,%6,%7},{%8,%9},{%0,%1,%2,%3};"
        : "+f"(c[0]), "+f"(c[1]), "+f"(c[2]), "+f"(c[3])
        : "r"(a0), "r"(a1), "r"(a2), "r"(a3), "r"(b0), "r"(b1));
}
// 3-term compensated bf16 product: Ah*Bl + Al*Bh + Ah*Bh
__device__ __forceinline__ void mma16x3(float c[4],
                                        const uint32_t ah[4], const uint32_t al[4],
                                        uint32_t bh0, uint32_t bh1,
                                        uint32_t bl0, uint32_t bl1) {
    mma16(c, ah[0], ah[1], ah[2], ah[3], bl0, bl1);
    mma16(c, al[0], al[1], al[2], al[3], bh0, bh1);
    mma16(c, ah[0], ah[1], ah[2], ah[3], bh0, bh1);
}

// =================================================================================
// Projection (tf32x3): C = A @ W^T + bias.
// MODE 1: fused l2norm (Q/K, N=128), dst 0 -> g_pq, dst 1 -> g_pk.
// MODE 0: V, writes transposed g_pvT[b][d][l].
// =================================================================================
template <int MODE>
__global__ __launch_bounds__(256) void proj_kernel(const float* __restrict__ A,
                                                   const float* __restrict__ W,
                                                   const float* __restrict__ bias,
                                                   int dst, int N) {
    extern __shared__ __align__(16) uint32_t sm[];
    uint32_t* Ah = sm;                    // [128][36]
    uint32_t* Al = Ah + 128 * 36;
    uint32_t* Wh = Al + 128 * 36;
    uint32_t* Wl = Wh + 128 * 36;
    float* pnorm = (float*)(Wl + 128 * 36);  // [2][128]
    float* stage = (float*)sm;               // MODE 0 epilogue overlay [128][131]

    float* C = (dst == 0) ? g_pq : g_pk;

    const int tid = threadIdx.x;
    const int lane = tid & 31, w = tid >> 5;
    const int g = lane >> 2, tig = lane & 3;
    const int wq = w >> 1, ws = w & 1;
    const int bm = blockIdx.y * 128, bn = blockIdx.x * 128;

    float c[2][8][4];
#pragma unroll
    for (int mt = 0; mt < 2; mt++)
#pragma unroll
        for (int j = 0; j < 8; j++)
#pragma unroll
            for (int v = 0; v < 4; v++) c[mt][j][v] = 0.f;

    for (int k0 = 0; k0 < DIM; k0 += 32) {
        __syncthreads();
#pragma unroll
        for (int t = 0; t < 4; t++) {
            int u = tid + t * 256;
            int m = u >> 3, kq = (u & 7) << 2;
            float4 va = *(const float4*)(A + (size_t)(bm + m) * DIM + k0 + kq);
            split_tf(va.x, Ah[m * 36 + kq + 0], Al[m * 36 + kq + 0]);
            split_tf(va.y, Ah[m * 36 + kq + 1], Al[m * 36 + kq + 1]);
            split_tf(va.z, Ah[m * 36 + kq + 2], Al[m * 36 + kq + 2]);
            split_tf(va.w, Ah[m * 36 + kq + 3], Al[m * 36 + kq + 3]);
            float4 vw = *(const float4*)(W + (size_t)(bn + m) * DIM + k0 + kq);
            split_tf(vw.x, Wh[m * 36 + kq + 0], Wl[m * 36 + kq + 0]);
            split_tf(vw.y, Wh[m * 36 + kq + 1], Wl[m * 36 + kq + 1]);
            split_tf(vw.z, Wh[m * 36 + kq + 2], Wl[m * 36 + kq + 2]);
            split_tf(vw.w, Wh[m * 36 + kq + 3], Wl[m * 36 + kq + 3]);
        }
        __syncthreads();
#pragma unroll
        for (int kk = 0; kk < 4; kk++) {
            const int kc = kk * 8 + tig;
            uint32_t ah[2][4], al[2][4];
#pragma unroll
            for (int mt = 0; mt < 2; mt++) {
                int r = wq * 32 + mt * 16 + g;
                ah[mt][0] = Ah[r * 36 + kc];
                ah[mt][1] = Ah[(r + 8) * 36 + kc];
                ah[mt][2] = Ah[r * 36 + kc + 4];
                ah[mt][3] = Ah[(r + 8) * 36 + kc + 4];
                al[mt][0] = Al[r * 36 + kc];
                al[mt][1] = Al[(r + 8) * 36 + kc];
                al[mt][2] = Al[r * 36 + kc + 4];
                al[mt][3] = Al[(r + 8) * 36 + kc + 4];
            }
#pragma unroll
            for (int j = 0; j < 8; j++) {
                int n = ws * 64 + j * 8 + g;
                uint32_t bh0 = Wh[n * 36 + kc], bh1 = Wh[n * 36 + kc + 4];
                uint32_t bl0 = Wl[n * 36 + kc], bl1 = Wl[n * 36 + kc + 4];
#pragma unroll
                for (int mt = 0; mt < 2; mt++) {
                    mma8(c[mt][j], ah[mt][0], ah[mt][1], ah[mt][2], ah[mt][3], bl0, bl1);
                    mma8(c[mt][j], al[mt][0], al[mt][1], al[mt][2], al[mt][3], bh0, bh1);
                    mma8(c[mt][j], ah[mt][0], ah[mt][1], ah[mt][2], ah[mt][3], bh0, bh1);
                }
            }
        }
    }

    // bias
#pragma unroll
    for (int j = 0; j < 8; j++) {
        int col = bn + ws * 64 + j * 8 + 2 * tig;
        float b0 = bias[col], b1 = bias[col + 1];
#pragma unroll
        for (int mt = 0; mt < 2; mt++) {
            c[mt][j][0] += b0; c[mt][j][1] += b1;
            c[mt][j][2] += b0; c[mt][j][3] += b1;
        }
    }

    if (MODE == 1) {
        // fused l2norm across the 128-wide row (one block spans it)
        float ss[2][2];
#pragma unroll
        for (int mt = 0; mt < 2; mt++) { ss[mt][0] = 0.f; ss[mt][1] = 0.f; }
#pragma unroll
        for (int mt = 0; mt < 2; mt++)
#pragma unroll
            for (int j = 0; j < 8; j++) {
                ss[mt][0] += c[mt][j][0] * c[mt][j][0] + c[mt][j][1] * c[mt][j][1];
                ss[mt][1] += c[mt][j][2] * c[mt][j][2] + c[mt][j][3] * c[mt][j][3];
            }
#pragma unroll
        for (int mt = 0; mt < 2; mt++)
#pragma unroll
            for (int h = 0; h < 2; h++) {
                ss[mt][h] += __shfl_xor_sync(0xffffffffu, ss[mt][h], 1);
                ss[mt][h] += __shfl_xor_sync(0xffffffffu, ss[mt][h], 2);
            }
        if (tig == 0) {
#pragma unroll
            for (int mt = 0; mt < 2; mt++)
#pragma unroll
                for (int h = 0; h < 2; h++)
                    pnorm[ws * 128 + wq * 32 + mt * 16 + g + 8 * h] = ss[mt][h];
        }
        __syncthreads();
#pragma unroll
        for (int mt = 0; mt < 2; mt++)
#pragma unroll
            for (int h = 0; h < 2; h++) {
                int row = wq * 32 + mt * 16 + g + 8 * h;
                float n2 = pnorm[row] + pnorm[128 + row];
                float scale = 1.f / fmaxf(sqrtf(n2), 1e-12f);
                size_t base = (size_t)(bm + row) * N + bn + ws * 64;
#pragma unroll
                for (int j = 0; j < 8; j++)
                    *(float2*)(C + base + j * 8 + 2 * tig) =
                        make_float2(c[mt][j][2 * h] * scale,
                                    c[mt][j][2 * h + 1] * scale);
            }
    } else {
        // V: stage to smem, then transposed write to g_pvT[b][d][l]
        __syncthreads();   // done with Ah..Wl before overlay
#pragma unroll
        for (int mt = 0; mt < 2; mt++)
#pragma unroll
            for (int h = 0; h < 2; h++) {
                int row = wq * 32 + mt * 16 + g + 8 * h;
#pragma unroll
                for (int j = 0; j < 8; j++) {
                    int col = ws * 64 + j * 8 + 2 * tig;
                    stage[row * 131 + col]     = c[mt][j][2 * h];
                    stage[row * 131 + col + 1] = c[mt][j][2 * h + 1];
                }
            }
        __syncthreads();
        const int lbase = bm >> 2;      // token m = 4*l + b
#pragma unroll
        for (int t = 0; t < 16; t++) {
            int task = tid + t * 256;          // 4096 tasks
            int col = task >> 3;               // 0..511 : b*128 + d
            int lq = task & 7;
            int bb = col >> 7, d = col & 127;
            float4 v;
            v.x = stage[(16 * lq + 0 * 4 + bb) * 131 + d];
            v.y = stage[(16 * lq + 1 * 4 + bb) * 131 + d];
            v.z = stage[(16 * lq + 2 * 4 + bb) * 131 + d];
            v.w = stage[(16 * lq + 3 * 4 + bb) * 131 + d];
            *(float4*)(g_pvT + ((size_t)bb * DIM + bn + d) * LQ + lbase + 4 * lq) = v;
        }
    }
}

// =================================================================================
// Scores + online softmax (bf16 3-term, m16n8k16).
// =================================================================================
__global__ __launch_bounds__(256) void scores_kernel() {
    extern __shared__ __align__(16) uint32_t sm[];
    uint32_t* Qh = sm;                    // [128][68] packed bf16 pairs along k
    uint32_t* Ql = Qh + 128 * 68;
    uint32_t* Kh = Ql + 128 * 68;         // [128][68]
    uint32_t* Kl = Kh + 128 * 68;
    float* fb    = (float*)(Kl + 128 * 68);
    float* m_run = fb;            // [128]
    float* s_run = fb + 128;      // [128]
    float* mnew  = fb + 256;      // [128]
    float* pmax  = fb + 384;      // [2][128]
    float* psum  = fb + 640;      // [2][128]
    float* mch   = fb + 896;      // [128][33]

    const int tid = threadIdx.x;
    const int lane = tid & 31, w = tid >> 5;
    const int g = lane >> 2, tig = lane & 3;
    const int wq = w >> 1, ws = w & 1;
    const int b = blockIdx.y;
    const int q0 = blockIdx.x * 128;

    if (tid < 128) { m_run[tid] = -INFINITY; s_run[tid] = 0.f; }

    // Q resident (hi/lo packed pairs)
#pragma unroll
    for (int t = 0; t < 16; t++) {
        int u = tid + t * 256;
        int q = u >> 5, f4 = u & 31;
        float4 v = *(const float4*)(g_pq + (size_t)((q0 + q) * NB + b) * KDIM + 4 * f4);
        split_pack(v.x, v.y, Qh[q * 68 + 2 * f4],     Ql[q * 68 + 2 * f4]);
        split_pack(v.z, v.w, Qh[q * 68 + 2 * f4 + 1], Ql[q * 68 + 2 * f4 + 1]);
    }

    for (int ch = 0; ch < NCH; ch++) {
        const int s0 = ch * 128;
        __syncthreads();
#pragma unroll
        for (int t = 0; t < 16; t++) {
            int u = tid + t * 256;
            int s = u >> 5, f4 = u & 31;
            float4 v = *(const float4*)(g_pk + (size_t)((s0 + s) * NB + b) * KDIM + 4 * f4);
            split_pack(v.x, v.y, Kh[s * 68 + 2 * f4],     Kl[s * 68 + 2 * f4]);
            split_pack(v.z, v.w, Kh[s * 68 + 2 * f4 + 1], Kl[s * 68 + 2 * f4 + 1]);
        }
        __syncthreads();

        float c[2][8][4];
#pragma unroll
        for (int mt = 0; mt < 2; mt++)
#pragma unroll
            for (int j = 0; j < 8; j++)
#pragma unroll
                for (int v = 0; v < 4; v++) c[mt][j][v] = 0.f;

#pragma unroll
        for (int kk = 0; kk < 8; kk++) {        // 8 x k16 = 128
            const int c0 = kk * 8;
            uint32_t ah[2][4], al[2][4];
#pragma unroll
            for (int mt = 0; mt < 2; mt++) {
                int r = wq * 32 + mt * 16 + g;
                ah[mt][0] = Qh[r * 68 + c0 + tig];
                ah[mt][1] = Qh[(r + 8) * 68 + c0 + tig];
                ah[mt][2] = Qh[r * 68 + c0 + 4 + tig];
                ah[mt][3] = Qh[(r + 8) * 68 + c0 + 4 + tig];
                al[mt][0] = Ql[r * 68 + c0 + tig];
                al[mt][1] = Ql[(r + 8) * 68 + c0 + tig];
                al[mt][2] = Ql[r * 68 + c0 + 4 + tig];
                al[mt][3] = Ql[(r + 8) * 68 + c0 + 4 + tig];
            }
#pragma unroll
            for (int j = 0; j < 8; j++) {
                int n = ws * 64 + j * 8 + g;
                uint32_t bh0 = Kh[n * 68 + c0 + tig], bh1 = Kh[n * 68 + c0 + 4 + tig];
                uint32_t bl0 = Kl[n * 68 + c0 + tig], bl1 = Kl[n * 68 + c0 + 4 + tig];
#pragma unroll
                for (int mt = 0; mt < 2; mt++)
                    mma16x3(c[mt][j], ah[mt], al[mt], bh0, bh1, bl0, bl1);
            }
        }

        // ---- softmax over this 128-key chunk ----
        float rmax[2][2];
#pragma unroll
        for (int mt = 0; mt < 2; mt++)
#pragma unroll
            for (int h = 0; h < 2; h++) {
                float m = -INFINITY;
#pragma unroll
                for (int j = 0; j < 8; j++)
                    m = fmaxf(m, fmaxf(c[mt][j][2 * h], c[mt][j][2 * h + 1]));
                m = fmaxf(m, __shfl_xor_sync(0xffffffffu, m, 1));
                m = fmaxf(m, __shfl_xor_sync(0xffffffffu, m, 2));
                rmax[mt][h] = m;
            }
        if (tig == 0) {
#pragma unroll
            for (int mt = 0; mt < 2; mt++)
#pragma unroll
                for (int h = 0; h < 2; h++)
                    pmax[ws * 128 + wq * 32 + mt * 16 + g + 8 * h] = rmax[mt][h];
        }
        __syncthreads();
        if (tid < 128) {
            float mo = m_run[tid];
            float mn = fmaxf(mo, 30.f * fmaxf(pmax[tid], pmax[128 + tid]));
            mnew[tid] = mn;
            m_run[tid] = mn;
            s_run[tid] *= __expf(mo - mn);
            mch[tid * 33 + ch] = mn;
        }
        __syncthreads();
#pragma unroll
        for (int mt = 0; mt < 2; mt++)
#pragma unroll
            for (int h = 0; h < 2; h++) {
                int row = wq * 32 + mt * 16 + g + 8 * h;
                float mr = mnew[row];
                size_t base = ((size_t)b * LQ + q0 + row) * LQ + s0 + ws * 64;
                float rs = 0.f;
#pragma unroll
                for (int j = 0; j < 8; j++) {
                    float e0 = __expf(fmaf(30.f, c[mt][j][2 * h], -mr));
                    float e1 = __expf(fmaf(30.f, c[mt][j][2 * h + 1], -mr));
                    rs += e0 + e1;
                    *(float2*)(g_sc + base + j * 8 + 2 * tig) = make_float2(e0, e1);
                }
                rs += __shfl_xor_sync(0xffffffffu, rs, 1);
                rs += __shfl_xor_sync(0xffffffffu, rs, 2);
                if (tig == 0) psum[ws * 128 + row] = rs;
            }
        __syncthreads();
        if (tid < 128) s_run[tid] += psum[tid] + psum[128 + tid];
    }

    __syncthreads();
    if (tid < 128) s_run[tid] = 1.f / s_run[tid];
    __syncthreads();
#pragma unroll
    for (int t = 0; t < 16; t++) {
        int u = tid + t * 256;
        int q = u >> 5, ch = u & 31;
        g_corr[((size_t)b * LQ + q0 + q) * NCH + ch] =
            __expf(mch[q * 33 + ch] - m_run[q]) * s_run[q];
    }
}

// =================================================================================
// out = P @ V (bf16 3-term). P rebuilt as g_sc * corr; V read from g_pvT[b][d][l]
// so both operands load as packed k-pairs. Block 128q x 128d, 64-key subtiles.
// =================================================================================
__global__ __launch_bounds__(256) void out_kernel(float* __restrict__ out) {
    extern __shared__ __align__(16) uint32_t sm[];
    uint32_t* Ph = sm;              // [128 q][36] packed pairs along s (64 s)
    uint32_t* Pl = Ph + 128 * 36;
    uint32_t* Vh = Pl + 128 * 36;   // [128 d][36] packed pairs along s
    uint32_t* Vl = Vh + 128 * 36;
    float* csm = (float*)(Vl + 128 * 36);  // [128]

    const int tid = threadIdx.x;
    const int lane = tid & 31, w = tid >> 5;
    const int g = lane >> 2, tig = lane & 3;
    const int wq = w >> 1, ws = w & 1;
    const int b = blockIdx.z;
    const int q0 = blockIdx.y * 128;
    const int d0 = blockIdx.x * 128;

    float c[2][8][4];
#pragma unroll
    for (int mt = 0; mt < 2; mt++)
#pragma unroll
        for (int j = 0; j < 8; j++)
#pragma unroll
            for (int v = 0; v < 4; v++) c[mt][j][v] = 0.f;

    for (int ch = 0; ch < NCH; ch++) {
        __syncthreads();
        if (tid < 128)
            csm[tid] = g_corr[((size_t)b * LQ + q0 + tid) * NCH + ch];
        for (int sh = 0; sh < 2; sh++) {
            const int s0 = ch * 128 + sh * 64;
            __syncthreads();
#pragma unroll
            for (int t = 0; t < 8; t++) {
                int u = tid + t * 256;
                int q = u >> 4, f4 = u & 15;
                float4 v = *(const float4*)(g_sc +
                        ((size_t)b * LQ + q0 + q) * LQ + s0 + 4 * f4);
                float f = csm[q];
                split_pack(v.x * f, v.y * f, Ph[q * 36 + 2 * f4], Pl[q * 36 + 2 * f4]);
                split_pack(v.z * f, v.w * f, Ph[q * 36 + 2 * f4 + 1],
                           Pl[q * 36 + 2 * f4 + 1]);
            }
#pragma unroll
            for (int t = 0; t < 8; t++) {
                int u = tid + t * 256;
                int d = u >> 4, f4 = u & 15;
                float4 v = *(const float4*)(g_pvT +
                        ((size_t)b * DIM + d0 + d) * LQ + s0 + 4 * f4);
                split_pack(v.x, v.y, Vh[d * 36 + 2 * f4], Vl[d * 36 + 2 * f4]);
                split_pack(v.z, v.w, Vh[d * 36 + 2 * f4 + 1], Vl[d * 36 + 2 * f4 + 1]);
            }
            __syncthreads();
#pragma unroll
            for (int kk = 0; kk < 4; kk++) {      // 4 x k16 = 64 keys
                const int c0 = kk * 8;
                uint32_t ah[2][4], al[2][4];
#pragma unroll
                for (int mt = 0; mt < 2; mt++) {
                    int r = wq * 32 + mt * 16 + g;
                    ah[mt][0] = Ph[r * 36 + c0 + tig];
                    ah[mt][1] = Ph[(r + 8) * 36 + c0 + tig];
                    ah[mt][2] = Ph[r * 36 + c0 + 4 + tig];
                    ah[mt][3] = Ph[(r + 8) * 36 + c0 + 4 + tig];
                    al[mt][0] = Pl[r * 36 + c0 + tig];
                    al[mt][1] = Pl[(r + 8) * 36 + c0 + tig];
                    al[mt][2] = Pl[r * 36 + c0 + 4 + tig];
                    al[mt][3] = Pl[(r + 8) * 36 + c0 + 4 + tig];
                }
#pragma unroll
                for (int j = 0; j < 8; j++) {
                    int n = ws * 64 + j * 8 + g;
                    uint32_t bh0 = Vh[n * 36 + c0 + tig], bh1 = Vh[n * 36 + c0 + 4 + tig];
                    uint32_t bl0 = Vl[n * 36 + c0 + tig], bl1 = Vl[n * 36 + c0 + 4 + tig];
#pragma unroll
                    for (int mt = 0; mt < 2; mt++)
                        mma16x3(c[mt][j], ah[mt], al[mt], bh0, bh1, bl0, bl1);
                }
            }
        }
    }

#pragma unroll
    for (int mt = 0; mt < 2; mt++)
#pragma unroll
        for (int h = 0; h < 2; h++) {
            int row = wq * 32 + mt * 16 + g + 8 * h;
            size_t base = ((size_t)(q0 + row) * NB + b) * DIM + d0 + ws * 64;
#pragma unroll
            for (int j = 0; j < 8; j++)
                *(float2*)(out + base + j * 8 + 2 * tig) =
                    make_float2(c[mt][j][2 * h], c[mt][j][2 * h + 1]);
        }
}

// =================================================================================
extern "C" void kernel_launch(void* const* d_in, const int* in_sizes, int n_in,
                              void* d_out, int out_size) {
    (void)in_sizes; (void)n_in; (void)out_size;
    const float* query = (const float*)d_in[0];
    const float* key   = (const float*)d_in[1];
    const float* value = (const float*)d_in[2];
    const float* WKw   = (const float*)d_in[3];
    const float* WKb   = (const float*)d_in[4];
    const float* WVw   = (const float*)d_in[5];
    const float* WVb   = (const float*)d_in[6];
    float* out = (float*)d_out;

    const size_t SMP = (size_t)(4 * 128 * 36 + 256) * 4;         //  74,752
    const size_t SMS = (size_t)(4 * 128 * 68 + 5120) * 4;        // 159,744
    const size_t SMO = (size_t)(4 * 128 * 36 + 128) * 4;         //  74,240

    cudaFuncSetAttribute(proj_kernel<0>,
                         cudaFuncAttributeMaxDynamicSharedMemorySize, (int)SMP);
    cudaFuncSetAttribute(proj_kernel<1>,
                         cudaFuncAttributeMaxDynamicSharedMemorySize, (int)SMP);
    cudaFuncSetAttribute(scores_kernel,
                         cudaFuncAttributeMaxDynamicSharedMemorySize, (int)SMS);
    cudaFuncSetAttribute(out_kernel,
                         cudaFuncAttributeMaxDynamicSharedMemorySize, (int)SMO);

    proj_kernel<1><<<dim3(1, 128), 256, SMP>>>(query, WKw, WKb, 0, KDIM);
    proj_kernel<1><<<dim3(1, 128), 256, SMP>>>(key,   WKw, WKb, 1, KDIM);
    proj_kernel<0><<<dim3(4, 128), 256, SMP>>>(value, WVw, WVb, 2, DIM);
    scores_kernel<<<dim3(LQ / 128, NB), 256, SMS>>>();
    out_kernel<<<dim3(DIM / 128, LQ / 128, NB), 256, SMO>>>(out);
}

// round 5
// speedup vs baseline: 2.6362x; 1.1358x over previous
#include <cuda_runtime.h>
#include <cuda_bf16.h>
#include <math.h>
#include <stdint.h>
#include <stddef.h>

#define LQ   4096
#define NB   4
#define DIM  512
#define KDIM 128
#define MTOT (LQ * NB)
#define LH   (LQ / 2)      // 2048 key-pairs

// ---------------- scratch (all packed bf16 hi/lo pair arrays) ----------------
__device__ uint32_t g_qh[(size_t)MTOT * 64];            // 4 MB  normalized Q, pairs along k
__device__ uint32_t g_ql[(size_t)MTOT * 64];
__device__ uint32_t g_kh[(size_t)MTOT * 64];            // normalized K
__device__ uint32_t g_kl[(size_t)MTOT * 64];
__device__ uint32_t g_vh[(size_t)NB * DIM * LH];        // 16 MB V^T [b][d][l-pairs]
__device__ uint32_t g_vl[(size_t)NB * DIM * LH];
__device__ uint32_t g_sph[(size_t)NB * LQ * LH];        // 134 MB P = exp(30s-30) pairs along s
__device__ uint32_t g_spl[(size_t)NB * LQ * LH];
__device__ float    g_psum[(size_t)MTOT * 8];           // row-sum partials (4 ks x 2 ws)

// ---------------- tf32 helpers (projections) ----------------
__device__ __forceinline__ uint32_t f2tf(float x) {
    uint32_t u;
    asm("cvt.rna.tf32.f32 %0, %1;" : "=r"(u) : "f"(x));
    return u;
}
__device__ __forceinline__ void split_tf(float x, uint32_t& h, uint32_t& l) {
    h = f2tf(x);
    l = f2tf(x - __uint_as_float(h));
}
__device__ __forceinline__ void mma8(float c[4], uint32_t a0, uint32_t a1,
                                     uint32_t a2, uint32_t a3,
                                     uint32_t b0, uint32_t b1) {
    asm volatile(
        "mma.sync.aligned.m16n8k8.row.col.f32.tf32.tf32.f32 "
        "{%0,%1,%2,%3},{%4,%5,%6,%7},{%8,%9},{%0,%1,%2,%3};"
        : "+f"(c[0]), "+f"(c[1]), "+f"(c[2]), "+f"(c[3])
        : "r"(a0), "r"(a1), "r"(a2), "r"(a3), "r"(b0), "r"(b1));
}

// ---------------- bf16 helpers ----------------
__device__ __forceinline__ void split_pack(float x, float y,
                                           uint32_t& h, uint32_t& l) {
    __nv_bfloat16 bx = __float2bfloat16_rn(x);
    __nv_bfloat16 by = __float2bfloat16_rn(y);
    float rx = x - __bfloat162float(bx);
    float ry = y - __bfloat162float(by);
    __nv_bfloat16 cx = __float2bfloat16_rn(rx);
    __nv_bfloat16 cy = __float2bfloat16_rn(ry);
    h = ((uint32_t)__bfloat16_as_ushort(by) << 16) | __bfloat16_as_ushort(bx);
    l = ((uint32_t)__bfloat16_as_ushort(cy) << 16) | __bfloat16_as_ushort(cx);
}
__device__ __forceinline__ void mma16(float c[4], uint32_t a0, uint32_t a1,
                                      uint32_t a2, uint32_t a3,
                                      uint32_t b0, uint32_t b1) {
    asm volatile(
        "mma.sync.aligned.m16n8k16.row.col.f32.bf16.bf16.f32 "
        "{%0,%1,%2,%3},{%4,%5,%6,%7},{%8,%9},{%0,%1,%2,%3};"
        : "+f"(c[0]), "+f"(c[1]), "+f"(c[2]), "+f"(c[3])
        : "r"(a0), "r"(a1), "r"(a2), "r"(a3), "r"(b0), "r"(b1));
}
__device__ __forceinline__ void mma16x3(float c[4],
                                        const uint32_t ah[4], const uint32_t al[4],
                                        uint32_t bh0, uint32_t bh1,
                                        uint32_t bl0, uint32_t bl1) {
    mma16(c, ah[0], ah[1], ah[2], ah[3], bl0, bl1);
    mma16(c, al[0], al[1], al[2], al[3], bh0, bh1);
    mma16(c, ah[0], ah[1], ah[2], ah[3], bh0, bh1);
}

// =================================================================================
// Projection (tf32x3): C = A @ W^T + bias.
// MODE 1: fused l2norm, packed hi/lo epilogue -> g_qh/g_ql (dst 0) or g_kh/g_kl.
// MODE 0: V, transposed + packed epilogue -> g_vh/g_vl [b][d][l-pairs].
// =================================================================================
template <int MODE>
__global__ __launch_bounds__(256) void proj_kernel(const float* __restrict__ A,
                                                   const float* __restrict__ W,
                                                   const float* __restrict__ bias,
                                                   int dst) {
    extern __shared__ __align__(16) uint32_t sm[];
    uint32_t* Ah = sm;                    // [128][36]
    uint32_t* Al = Ah + 128 * 36;
    uint32_t* Wh = Al + 128 * 36;
    uint32_t* Wl = Wh + 128 * 36;
    float* pnorm = (float*)(Wl + 128 * 36);  // [2][128]
    float* stage = (float*)sm;               // MODE 0 epilogue overlay [128][131]

    const int tid = threadIdx.x;
    const int lane = tid & 31, w = tid >> 5;
    const int g = lane >> 2, tig = lane & 3;
    const int wq = w >> 1, ws = w & 1;
    const int bm = blockIdx.y * 128, bn = blockIdx.x * 128;

    float c[2][8][4];
#pragma unroll
    for (int mt = 0; mt < 2; mt++)
#pragma unroll
        for (int j = 0; j < 8; j++)
#pragma unroll
            for (int v = 0; v < 4; v++) c[mt][j][v] = 0.f;

    for (int k0 = 0; k0 < DIM; k0 += 32) {
        __syncthreads();
#pragma unroll
        for (int t = 0; t < 4; t++) {
            int u = tid + t * 256;
            int m = u >> 3, kq = (u & 7) << 2;
            float4 va = *(const float4*)(A + (size_t)(bm + m) * DIM + k0 + kq);
            split_tf(va.x, Ah[m * 36 + kq + 0], Al[m * 36 + kq + 0]);
            split_tf(va.y, Ah[m * 36 + kq + 1], Al[m * 36 + kq + 1]);
            split_tf(va.z, Ah[m * 36 + kq + 2], Al[m * 36 + kq + 2]);
            split_tf(va.w, Ah[m * 36 + kq + 3], Al[m * 36 + kq + 3]);
            float4 vw = *(const float4*)(W + (size_t)(bn + m) * DIM + k0 + kq);
            split_tf(vw.x, Wh[m * 36 + kq + 0], Wl[m * 36 + kq + 0]);
            split_tf(vw.y, Wh[m * 36 + kq + 1], Wl[m * 36 + kq + 1]);
            split_tf(vw.z, Wh[m * 36 + kq + 2], Wl[m * 36 + kq + 2]);
            split_tf(vw.w, Wh[m * 36 + kq + 3], Wl[m * 36 + kq + 3]);
        }
        __syncthreads();
#pragma unroll
        for (int kk = 0; kk < 4; kk++) {
            const int kc = kk * 8 + tig;
            uint32_t ah[2][4], al[2][4];
#pragma unroll
            for (int mt = 0; mt < 2; mt++) {
                int r = wq * 32 + mt * 16 + g;
                ah[mt][0] = Ah[r * 36 + kc];
                ah[mt][1] = Ah[(r + 8) * 36 + kc];
                ah[mt][2] = Ah[r * 36 + kc + 4];
                ah[mt][3] = Ah[(r + 8) * 36 + kc + 4];
                al[mt][0] = Al[r * 36 + kc];
                al[mt][1] = Al[(r + 8) * 36 + kc];
                al[mt][2] = Al[r * 36 + kc + 4];
                al[mt][3] = Al[(r + 8) * 36 + kc + 4];
            }
#pragma unroll
            for (int j = 0; j < 8; j++) {
                int n = ws * 64 + j * 8 + g;
                uint32_t bh0 = Wh[n * 36 + kc], bh1 = Wh[n * 36 + kc + 4];
                uint32_t bl0 = Wl[n * 36 + kc], bl1 = Wl[n * 36 + kc + 4];
#pragma unroll
                for (int mt = 0; mt < 2; mt++) {
                    mma8(c[mt][j], ah[mt][0], ah[mt][1], ah[mt][2], ah[mt][3], bl0, bl1);
                    mma8(c[mt][j], al[mt][0], al[mt][1], al[mt][2], al[mt][3], bh0, bh1);
                    mma8(c[mt][j], ah[mt][0], ah[mt][1], ah[mt][2], ah[mt][3], bh0, bh1);
                }
            }
        }
    }

    // bias
#pragma unroll
    for (int j = 0; j < 8; j++) {
        int col = bn + ws * 64 + j * 8 + 2 * tig;
        float b0 = bias[col], b1 = bias[col + 1];
#pragma unroll
        for (int mt = 0; mt < 2; mt++) {
            c[mt][j][0] += b0; c[mt][j][1] += b1;
            c[mt][j][2] += b0; c[mt][j][3] += b1;
        }
    }

    if (MODE == 1) {
        uint32_t* OH = (dst == 0) ? g_qh : g_kh;
        uint32_t* OL = (dst == 0) ? g_ql : g_kl;
        float ss[2][2];
#pragma unroll
        for (int mt = 0; mt < 2; mt++) { ss[mt][0] = 0.f; ss[mt][1] = 0.f; }
#pragma unroll
        for (int mt = 0; mt < 2; mt++)
#pragma unroll
            for (int j = 0; j < 8; j++) {
                ss[mt][0] += c[mt][j][0] * c[mt][j][0] + c[mt][j][1] * c[mt][j][1];
                ss[mt][1] += c[mt][j][2] * c[mt][j][2] + c[mt][j][3] * c[mt][j][3];
            }
#pragma unroll
        for (int mt = 0; mt < 2; mt++)
#pragma unroll
            for (int h = 0; h < 2; h++) {
                ss[mt][h] += __shfl_xor_sync(0xffffffffu, ss[mt][h], 1);
                ss[mt][h] += __shfl_xor_sync(0xffffffffu, ss[mt][h], 2);
            }
        if (tig == 0) {
#pragma unroll
            for (int mt = 0; mt < 2; mt++)
#pragma unroll
                for (int h = 0; h < 2; h++)
                    pnorm[ws * 128 + wq * 32 + mt * 16 + g + 8 * h] = ss[mt][h];
        }
        __syncthreads();
#pragma unroll
        for (int mt = 0; mt < 2; mt++)
#pragma unroll
            for (int h = 0; h < 2; h++) {
                int row = wq * 32 + mt * 16 + g + 8 * h;
                float n2 = pnorm[row] + pnorm[128 + row];
                float scale = 1.f / fmaxf(sqrtf(n2), 1e-12f);
                size_t base = (size_t)(bm + row) * 64 + ws * 32;
#pragma unroll
                for (int j = 0; j < 8; j++) {
                    uint32_t hh, ll;
                    split_pack(c[mt][j][2 * h] * scale, c[mt][j][2 * h + 1] * scale,
                               hh, ll);
                    OH[base + j * 4 + tig] = hh;
                    OL[base + j * 4 + tig] = ll;
                }
            }
    } else {
        // V: stage to smem, then transposed packed write to g_vh/g_vl [b][d][l-pairs]
        __syncthreads();
#pragma unroll
        for (int mt = 0; mt < 2; mt++)
#pragma unroll
            for (int h = 0; h < 2; h++) {
                int row = wq * 32 + mt * 16 + g + 8 * h;
#pragma unroll
                for (int j = 0; j < 8; j++) {
                    int col = ws * 64 + j * 8 + 2 * tig;
                    stage[row * 131 + col]     = c[mt][j][2 * h];
                    stage[row * 131 + col + 1] = c[mt][j][2 * h + 1];
                }
            }
        __syncthreads();
        // rows m = 4*l + b; l-pair (2pq, 2pq+1) -> stage rows 8pq+bb, 8pq+4+bb
#pragma unroll
        for (int t = 0; t < 32; t++) {
            int task = tid + t * 256;           // 8192 tasks: 512 cols x 16 pairs
            int pq = task & 15;
            int col = task >> 4;                // 0..511 : bb*128 + d
            int bb = col >> 7, d = col & 127;
            float v0 = stage[(8 * pq + bb) * 131 + d];
            float v1 = stage[(8 * pq + 4 + bb) * 131 + d];
            uint32_t hh, ll;
            split_pack(v0, v1, hh, ll);
            size_t idx = ((size_t)bb * DIM + bn + d) * LH + (bm >> 3) + pq;
            g_vh[idx] = hh;
            g_vl[idx] = ll;
        }
    }
}

// =================================================================================
// Scores (bf16 3-term): P = exp(30*dot - 30) stored packed hi/lo; per-row partial
// sums -> g_psum. Fixed max 30 (cosine scores <= 1) kills the online softmax.
// Block: 64 q-rows x 1024 keys (8 chunks of 128). Grid (64, NB, 4). 2 blocks/SM.
// =================================================================================
__global__ __launch_bounds__(256, 2) void scores_kernel() {
    extern __shared__ __align__(16) uint32_t sm[];
    uint32_t* Qh = sm;                  // [64][68]
    uint32_t* Ql = Qh + 64 * 68;
    uint32_t* Kh = Ql + 64 * 68;        // [128][68]
    uint32_t* Kl = Kh + 128 * 68;

    const int tid = threadIdx.x;
    const int lane = tid & 31, w = tid >> 5;
    const int g = lane >> 2, tig = lane & 3;
    const int wq = w >> 1, ws = w & 1;
    const int b = blockIdx.y;
    const int q0 = blockIdx.x * 64;
    const int ks = blockIdx.z;

    // Q tile (pure copy, packed pairs)
#pragma unroll
    for (int t = 0; t < 4; t++) {
        int u = tid + t * 256;
        int q = u >> 4, f4 = (u & 15) << 2;
        *(float4*)&Qh[q * 68 + f4] =
            *(const float4*)(g_qh + (size_t)((q0 + q) * NB + b) * 64 + f4);
        *(float4*)&Ql[q * 68 + f4] =
            *(const float4*)(g_ql + (size_t)((q0 + q) * NB + b) * 64 + f4);
    }

    float sacc[2] = {0.f, 0.f};

    for (int cl = 0; cl < 8; cl++) {
        const int s0 = (ks * 8 + cl) * 128;
        __syncthreads();
#pragma unroll
        for (int t = 0; t < 8; t++) {
            int u = tid + t * 256;
            int s = u >> 4, f4 = (u & 15) << 2;
            *(float4*)&Kh[s * 68 + f4] =
                *(const float4*)(g_kh + (size_t)((s0 + s) * NB + b) * 64 + f4);
            *(float4*)&Kl[s * 68 + f4] =
                *(const float4*)(g_kl + (size_t)((s0 + s) * NB + b) * 64 + f4);
        }
        __syncthreads();

        float c[8][4];
#pragma unroll
        for (int j = 0; j < 8; j++)
#pragma unroll
            for (int v = 0; v < 4; v++) c[j][v] = 0.f;

#pragma unroll
        for (int kk = 0; kk < 8; kk++) {        // 8 x k16 = 128
            const int c0 = kk * 8;
            const int r = wq * 16 + g;
            uint32_t ah[4], al[4];
            ah[0] = Qh[r * 68 + c0 + tig];
            ah[1] = Qh[(r + 8) * 68 + c0 + tig];
            ah[2] = Qh[r * 68 + c0 + 4 + tig];
            ah[3] = Qh[(r + 8) * 68 + c0 + 4 + tig];
            al[0] = Ql[r * 68 + c0 + tig];
            al[1] = Ql[(r + 8) * 68 + c0 + tig];
            al[2] = Ql[r * 68 + c0 + 4 + tig];
            al[3] = Ql[(r + 8) * 68 + c0 + 4 + tig];
#pragma unroll
            for (int j = 0; j < 8; j++) {
                int n = ws * 64 + j * 8 + g;
                uint32_t bh0 = Kh[n * 68 + c0 + tig], bh1 = Kh[n * 68 + c0 + 4 + tig];
                uint32_t bl0 = Kl[n * 68 + c0 + tig], bl1 = Kl[n * 68 + c0 + 4 + tig];
                mma16x3(c[j], ah, al, bh0, bh1, bl0, bl1);
            }
        }

        // exp + pack + store, accumulate row sums
#pragma unroll
        for (int h = 0; h < 2; h++) {
            int row = wq * 16 + g + 8 * h;
            size_t base = ((size_t)b * LQ + q0 + row) * LH + (s0 >> 1) + ws * 32;
#pragma unroll
            for (int j = 0; j < 8; j++) {
                float e0 = __expf(fmaf(30.f, c[j][2 * h], -30.f));
                float e1 = __expf(fmaf(30.f, c[j][2 * h + 1], -30.f));
                sacc[h] += e0 + e1;
                uint32_t hh, ll;
                split_pack(e0, e1, hh, ll);
                g_sph[base + j * 4 + tig] = hh;
                g_spl[base + j * 4 + tig] = ll;
            }
        }
    }

#pragma unroll
    for (int h = 0; h < 2; h++) {
        float v = sacc[h];
        v += __shfl_xor_sync(0xffffffffu, v, 1);
        v += __shfl_xor_sync(0xffffffffu, v, 2);
        if (tig == 0) {
            int row = wq * 16 + g + 8 * h;
            g_psum[((size_t)b * LQ + q0 + row) * 8 + ks * 2 + ws] = v;
        }
    }
}

// =================================================================================
// out = (P @ V) * (1/S) per row. Pure-copy operand loads (everything pre-split).
// Block 128q x 128d, 64-key stages. Grid (4, 32, NB). 2 blocks/SM.
// =================================================================================
__global__ __launch_bounds__(256, 2) void out_kernel(float* __restrict__ out) {
    extern __shared__ __align__(16) uint32_t sm[];
    uint32_t* Ph = sm;              // [128 q][36]
    uint32_t* Pl = Ph + 128 * 36;
    uint32_t* Vh = Pl + 128 * 36;   // [128 d][36]
    uint32_t* Vl = Vh + 128 * 36;
    float* csm = (float*)(Vl + 128 * 36);  // [128] 1/S

    const int tid = threadIdx.x;
    const int lane = tid & 31, w = tid >> 5;
    const int g = lane >> 2, tig = lane & 3;
    const int wq = w >> 1, ws = w & 1;
    const int b = blockIdx.z;
    const int q0 = blockIdx.y * 128;
    const int d0 = blockIdx.x * 128;

    if (tid < 128) {
        const float* ps = g_psum + ((size_t)b * LQ + q0 + tid) * 8;
        float S = ps[0] + ps[1] + ps[2] + ps[3] + ps[4] + ps[5] + ps[6] + ps[7];
        csm[tid] = 1.f / S;
    }

    float c[2][8][4];
#pragma unroll
    for (int mt = 0; mt < 2; mt++)
#pragma unroll
        for (int j = 0; j < 8; j++)
#pragma unroll
            for (int v = 0; v < 4; v++) c[mt][j][v] = 0.f;

    for (int st = 0; st < 64; st++) {
        const int p0 = st * 32;            // pair offset into s
        __syncthreads();
#pragma unroll
        for (int t = 0; t < 4; t++) {
            int u = tid + t * 256;
            int q = u >> 3, p4 = (u & 7) << 2;
            *(float4*)&Ph[q * 36 + p4] =
                *(const float4*)(g_sph + ((size_t)b * LQ + q0 + q) * LH + p0 + p4);
            *(float4*)&Pl[q * 36 + p4] =
                *(const float4*)(g_spl + ((size_t)b * LQ + q0 + q) * LH + p0 + p4);
        }
#pragma unroll
        for (int t = 0; t < 4; t++) {
            int u = tid + t * 256;
            int d = u >> 3, p4 = (u & 7) << 2;
            *(float4*)&Vh[d * 36 + p4] =
                *(const float4*)(g_vh + ((size_t)b * DIM + d0 + d) * LH + p0 + p4);
            *(float4*)&Vl[d * 36 + p4] =
                *(const float4*)(g_vl + ((size_t)b * DIM + d0 + d) * LH + p0 + p4);
        }
        __syncthreads();
#pragma unroll
        for (int kk = 0; kk < 4; kk++) {      // 4 x k16 = 64 keys
            const int c0 = kk * 8;
            uint32_t ah[2][4], al[2][4];
#pragma unroll
            for (int mt = 0; mt < 2; mt++) {
                int r = wq * 32 + mt * 16 + g;
                ah[mt][0] = Ph[r * 36 + c0 + tig];
                ah[mt][1] = Ph[(r + 8) * 36 + c0 + tig];
                ah[mt][2] = Ph[r * 36 + c0 + 4 + tig];
                ah[mt][3] = Ph[(r + 8) * 36 + c0 + 4 + tig];
                al[mt][0] = Pl[r * 36 + c0 + tig];
                al[mt][1] = Pl[(r + 8) * 36 + c0 + tig];
                al[mt][2] = Pl[r * 36 + c0 + 4 + tig];
                al[mt][3] = Pl[(r + 8) * 36 + c0 + 4 + tig];
            }
#pragma unroll
            for (int j = 0; j < 8; j++) {
                int n = ws * 64 + j * 8 + g;
                uint32_t bh0 = Vh[n * 36 + c0 + tig], bh1 = Vh[n * 36 + c0 + 4 + tig];
                uint32_t bl0 = Vl[n * 36 + c0 + tig], bl1 = Vl[n * 36 + c0 + 4 + tig];
#pragma unroll
                for (int mt = 0; mt < 2; mt++)
                    mma16x3(c[mt][j], ah[mt], al[mt], bh0, bh1, bl0, bl1);
            }
        }
    }

#pragma unroll
    for (int mt = 0; mt < 2; mt++)
#pragma unroll
        for (int h = 0; h < 2; h++) {
            int row = wq * 32 + mt * 16 + g + 8 * h;
            float scale = csm[row];
            size_t base = ((size_t)(q0 + row) * NB + b) * DIM + d0 + ws * 64;
#pragma unroll
            for (int j = 0; j < 8; j++)
                *(float2*)(out + base + j * 8 + 2 * tig) =
                    make_float2(c[mt][j][2 * h] * scale,
                                c[mt][j][2 * h + 1] * scale);
        }
}

// =================================================================================
extern "C" void kernel_launch(void* const* d_in, const int* in_sizes, int n_in,
                              void* d_out, int out_size) {
    (void)in_sizes; (void)n_in; (void)out_size;
    const float* query = (const float*)d_in[0];
    const float* key   = (const float*)d_in[1];
    const float* value = (const float*)d_in[2];
    const float* WKw   = (const float*)d_in[3];
    const float* WKb   = (const float*)d_in[4];
    const float* WVw   = (const float*)d_in[5];
    const float* WVb   = (const float*)d_in[6];
    float* out = (float*)d_out;

    const size_t SMP = (size_t)(4 * 128 * 36 + 256) * 4;           //  74,752
    const size_t SMS = (size_t)(2 * 64 * 68 + 2 * 128 * 68) * 4;   // 104,448
    const size_t SMO = (size_t)(4 * 128 * 36 + 128) * 4;           //  74,240

    cudaFuncSetAttribute(proj_kernel<0>,
                         cudaFuncAttributeMaxDynamicSharedMemorySize, (int)SMP);
    cudaFuncSetAttribute(proj_kernel<1>,
                         cudaFuncAttributeMaxDynamicSharedMemorySize, (int)SMP);
    cudaFuncSetAttribute(scores_kernel,
                         cudaFuncAttributeMaxDynamicSharedMemorySize, (int)SMS);
    cudaFuncSetAttribute(out_kernel,
                         cudaFuncAttributeMaxDynamicSharedMemorySize, (int)SMO);

    proj_kernel<1><<<dim3(1, 128), 256, SMP>>>(query, WKw, WKb, 0);
    proj_kernel<1><<<dim3(1, 128), 256, SMP>>>(key,   WKw, WKb, 1);
    proj_kernel<0><<<dim3(4, 128), 256, SMP>>>(value, WVw, WVb, 2);
    scores_kernel<<<dim3(LQ / 64, NB, 4), 256, SMS>>>();
    out_kernel<<<dim3(DIM / 128, LQ / 128, NB), 256, SMO>>>(out);
}